// round 6
// baseline (speedup 1.0000x reference)
#include <cuda_runtime.h>
#include <math.h>

// ---------------- problem constants ----------------
#define NB    32
#define NCOL  160
#define NOUT  10
#define OFF_DIST 320
#define OFF_PROB 5440
#define OFF_LOSS 10560

#define NBLK  444                 // 148 SMs * 3 blocks = one wave
#define NTICK 1056                // 32*(6+8+9+10) passes

// smem layout (words)
#define SXSTR 526                 // 512 + 14 pad; 526%32=14 -> distinct banks per channel
#define SXW   (8*SXSTR)           // 4208
#define SWW   258                 // uniform (even => aligned LDS.64), 258%32=2 conflict-free
#define SM_WORDS (SXW + 40*SWW)   // 14528
#define SM_BYTES (SM_WORDS*4)     // 58112 -> 3 blocks/SM

typedef unsigned long long ull;

__device__ unsigned g_d[NB*NCOL] = {};
__device__ unsigned g_q[NB*NCOL] = {};
__device__ unsigned g_tick = 0;
__device__ unsigned g_ctr  = 0;

__device__ __forceinline__ unsigned fenc(float f){unsigned u=__float_as_uint(f);return (u&0x80000000u)?~u:(u|0x80000000u);}
__device__ __forceinline__ float fdec(unsigned e){unsigned u=(e&0x80000000u)?(e&0x7fffffffu):~e;return __uint_as_float(u);}
__device__ __forceinline__ unsigned ienc(float f){ return ~fenc(f); }   // max(ienc) = min(f); 0 = +inf sentinel
__device__ __forceinline__ float idec(unsigned e){ return fdec(~e); }

__device__ __forceinline__ ull addf2(ull a, ull b){
    ull r; asm("add.rn.f32x2 %0, %1, %2;" : "=l"(r) : "l"(a), "l"(b)); return r;
}
__device__ __forceinline__ float lo32(ull v){ return __uint_as_float((unsigned)(v & 0xffffffffull)); }
__device__ __forceinline__ float hi32(ull v){ return __uint_as_float((unsigned)(v >> 32)); }

template<int PAR>
__device__ __forceinline__ ull ldx(const float* p) {
    if (PAR == 0) {
        return *(const ull*)p;
    } else {
        float a = p[0], b = p[1];
        ull r; asm("mov.b64 %0, {%1, %2};" : "=l"(r) : "f"(a), "f"(b));
        return r;
    }
}

// ---------------- one item = 8 windows of one parity (validated core) ----------------
template<int L, int M, int PAR, int SBASE>
__device__ __forceinline__ void item1(const float* __restrict__ sx, const float* __restrict__ sw,
                                      const float* __restrict__ pcm, int idx, int b)
{
    constexpr int NP   = L/2;
    constexpr int REM  = NP % 8;
    constexpr int MAIN = NP - REM;
    constexpr bool ODDL = (L & 1);
    constexpr float INVL = 1.0f/(float)L;

    int tl = idx / 40;
    int nc = idx - tl*40;
    int c  = nc & 7;
    const float* xr = sx + c*SXSTR + 16*tl + PAR;
    const float* wr = sw + nc*SWW;

    float prv[8];
#pragma unroll
    for (int k = 0; k < 8; k++) {
        int mm = 16*tl + 2*k + PAR;
        prv[k] = __ldg(&pcm[c*M + (mm < M ? mm : M-1)]);
    }

    ull xq[8], acc[8];
#pragma unroll
    for (int k = 0; k < 8; k++) { xq[k] = ldx<PAR>(xr + 2*k); acc[k] = 0ull; }

    for (int st = 0; st < MAIN; st += 8) {
#pragma unroll
        for (int u = 0; u < 8; u++) {
            ull wp = *(const ull*)(wr + 2*(st+u));
#pragma unroll
            for (int k = 0; k < 8; k++) {
                ull d = addf2(xq[(k+u)&7], wp);      // x + (-w)
                d &= 0x7FFFFFFF7FFFFFFFull;          // packed abs
                acc[k] = addf2(acc[k], d);
            }
            xq[u] = ldx<PAR>(xr + 2*(st+u) + 16);
        }
    }
#pragma unroll
    for (int u = 0; u < REM; u++) {
        ull wp = *(const ull*)(wr + 2*(MAIN+u));
#pragma unroll
        for (int k = 0; k < 8; k++) {
            ull d = addf2(xq[(k+u)&7], wp);
            d &= 0x7FFFFFFF7FFFFFFFull;
            acc[k] = addf2(acc[k], d);
        }
        xq[u&7] = ldx<PAR>(xr + 2*(MAIN+u) + 16);
    }

    float dmin = 3.4e38f, qmin = 3.4e38f;
#pragma unroll
    for (int k = 0; k < 8; k++) {
        int mm = 16*tl + 2*k + PAR;
        if (mm < M) {
            float ssum = lo32(acc[k]) + hi32(acc[k]);
            if (ODDL) ssum += fabsf(lo32(xq[(k+REM)&7]) + wr[L-1]);  // wr holds -w
            float d = ssum * INVL * prv[k];
            dmin = fminf(dmin, d);
            qmin = fminf(qmin, fabsf(d));
        }
    }
    atomicMax(&g_d[b*NCOL + SBASE + nc], ienc(dmin));
    atomicMax(&g_q[b*NCOL + SBASE + nc], ienc(qmin));
}

// ---------------- fused persistent kernel ----------------
__global__ __launch_bounds__(256, 3)
void k_all(const float* __restrict__ x,
           const float* __restrict__ w0, const float* __restrict__ w1,
           const float* __restrict__ w2, const float* __restrict__ w3,
           const float* __restrict__ p0, const float* __restrict__ p1,
           const float* __restrict__ p2, const float* __restrict__ p3,
           const float* __restrict__ Wout, float* __restrict__ out)
{
    extern __shared__ float sm[];
    float* sx = sm;
    float* sw = sm + SXW;
    __shared__ int sh_t;
    __shared__ unsigned s_old;

    int tid = threadIdx.x;
    int bx = blockIdx.x;

    // ---- block 0: losses first (independent of shapelet results) ----
    if (bx == 0) {
        float* sf   = sm;            // [640]
        float* sr   = sm + 640;      // [640]
        float* sval = sm + 1280;     // [256]
        float* sreg = sm + 1536;     // [256]

        float reg = 0.f;
        for (int i = tid; i < NOUT*NCOL; i += 256) reg += fabsf(Wout[i]);
        sreg[tid] = reg;

        const int Ls[4] = {52, 103, 154, 256};
        const float* wls[4] = {w0, w1, w2, w3};
        const signed char I1[10] = {0,0,0,0,1,1,1,2,2,3};
        const signed char J1[10] = {1,2,3,4,2,3,4,3,4,4};

        for (int u = tid; u < 640; u += 256) {
            int pp = u >> 1, h = u & 1;
            int s = pp / 80; int r = pp - s*80;
            int c = r / 10; int pr = r - c*10;
            int i = I1[pr], j = J1[pr];
            int L = Ls[s];
            const float* wa = wls[s] + (i*8 + c)*L;
            const float* wb = wls[s] + (j*8 + c)*L;
            int k0 = h ? (L >> 1) : 0;
            int k1 = h ? L : (L >> 1);
            float af = 0.f, ar = 0.f;
#pragma unroll 8
            for (int k = k0; k < k1; k++) {
                float t = wa[k] - wb[k];
                float df = t + 1e-6f, dr = 1e-6f - t;
                af += df*df; ar += dr*dr;
            }
            sf[u] = af; sr[u] = ar;
        }
        __syncthreads();
        float val = 0.f;
        for (int pp = tid; pp < 320; pp += 256) {
            float ssf = sf[2*pp] + sf[2*pp + 1];
            float ssr = sr[2*pp] + sr[2*pp + 1];
            val += (expf(-sqrtf(ssf)) + expf(-sqrtf(ssr))) * (1.f/200.f);
        }
        sval[tid] = val;
        __syncthreads();
        for (int off = 128; off; off >>= 1) {
            if (tid < off) { sval[tid] += sval[tid+off]; sreg[tid] += sreg[tid+off]; }
            __syncthreads();
        }
        if (tid == 0) out[OFF_LOSS] = 0.1f*(sreg[0]/1600.f) + 0.1f*sval[0];
        __syncthreads();
    }

    const float* wps[4] = {w0, w1, w2, w3};
    const float* pps[4] = {p0, p1, p2, p3};
    const int Lss[4] = {52, 103, 154, 256};

    int cur_b = -1, cur_s = -1;
    int t = bx;                       // static first ticket (expensive-first ordering)
    for (;;) {
        // decode ticket -> (set, batch, pass). Order: set3(192), set2(256), set1(288), set0(320)
        int s, b, pass;
        if (t < 192)      { s = 3; b = t/6;            pass = t - b*6; }
        else if (t < 448) { int u = t-192; s = 2; b = u/8;  pass = u - b*8; }
        else if (t < 736) { int u = t-448; s = 1; b = u/9;  pass = u - b*9; }
        else              { int u = t-736; s = 0; b = u/10; pass = u - b*10; }

        if (b != cur_b || s != cur_s) {
            __syncthreads();          // prior pass readers done before restage
            if (b != cur_b) {
                int wp_ = tid >> 5, lane = tid & 31;
                const float* row = x + (b*8 + wp_)*512;
                float v[16]; float sv = 0.f;
#pragma unroll
                for (int i = 0; i < 16; i++) { v[i] = row[lane + 32*i]; sv += v[i]; }
#pragma unroll
                for (int o = 16; o; o >>= 1) sv += __shfl_xor_sync(0xffffffffu, sv, o);
                float mu = sv * (1.f/512.f);
                float qq = 0.f;
#pragma unroll
                for (int i = 0; i < 16; i++) { float d = v[i]-mu; qq += d*d; }
#pragma unroll
                for (int o = 16; o; o >>= 1) qq += __shfl_xor_sync(0xffffffffu, qq, o);
                float sc = 1.f / (sqrtf(qq * (1.f/511.f)) + 1e-8f);
                float* orow = sx + wp_*SXSTR;
#pragma unroll
                for (int i = 0; i < 16; i++) orow[lane + 32*i] = (v[i]-mu)*sc;
                if (lane < SXSTR - 512) orow[512 + lane] = 0.f;
                cur_b = b;
            }
            if (s != cur_s) {
                int L = Lss[s];
                const float* wp = wps[s];
                for (int i2 = tid; i2 < 40*L; i2 += 256) {
                    int r = i2 / L, j = i2 - r*L;
                    sw[r*SWW + j] = -wp[i2];
                }
                cur_s = s;
            }
            __syncthreads();
        }

        int i = pass*256 + tid;
        switch (s) {
            case 0:
                if (i < 2320) {
                    if (i < 1160) item1< 52,461,0,  0>(sx, sw, pps[0], i, b);
                    else          item1< 52,461,1,  0>(sx, sw, pps[0], i-1160, b);
                }
                break;
            case 1:
                if (i < 2080) {
                    if (i < 1040) item1<103,410,0, 40>(sx, sw, pps[1], i, b);
                    else          item1<103,410,1, 40>(sx, sw, pps[1], i-1040, b);
                }
                break;
            case 2:
                if (i < 1840) {
                    if (i <  920) item1<154,359,0, 80>(sx, sw, pps[2], i, b);
                    else          item1<154,359,1, 80>(sx, sw, pps[2], i-920, b);
                }
                break;
            default:
                if (i < 1360) {
                    if (i <  680) item1<256,257,0,120>(sx, sw, pps[3], i, b);
                    else          item1<256,257,1,120>(sx, sw, pps[3], i-680, b);
                }
                break;
        }
        __syncthreads();              // all readers done before sh_t overwrite
        if (tid == 0) sh_t = (int)(atomicAdd(&g_tick, 1u) + NBLK);
        __syncthreads();
        t = sh_t;
        if (t >= NTICK) break;
    }

    // ---- completion counter: last block finalizes ----
    __threadfence();
    __syncthreads();
    if (tid == 0) s_old = atomicAdd(&g_ctr, 1u);
    __syncthreads();
    if (s_old != NBLK - 1) return;

    __threadfence();
    float* sprob = sm;              // [5120]
    float* swout = sm + 5120;       // [1600]
    for (int i = tid; i < NB*NCOL; i += 256) {
        unsigned de = atomicMax(&g_d[i], 0u);   // L2-coherent read
        unsigned qe = atomicMax(&g_q[i], 0u);
        g_d[i] = 0u; g_q[i] = 0u;               // reset for next replay
        float qv = idec(qe);
        float p = expf(-qv*qv);
        out[OFF_DIST + i] = idec(de);
        out[OFF_PROB + i] = p;
        sprob[i] = p;
    }
    for (int i = tid; i < NOUT*NCOL; i += 256) swout[i] = Wout[i];
    __syncthreads();
    for (int tt = tid; tt < NB*NOUT; tt += 256) {
        int bb = tt / NOUT, o = tt - bb*NOUT;
        const float* pr = sprob + bb*NCOL;
        const float* wr = swout + o*NCOL;
        float acc = 0.f;
#pragma unroll 8
        for (int j = 0; j < NCOL; j++) acc += pr[j]*wr[j];
        out[bb*NOUT + o] = acc;
    }
    if (tid == 0) { g_tick = 0u; g_ctr = 0u; }
}

// ---------------- launch ----------------
extern "C" void kernel_launch(void* const* d_in, const int* in_sizes, int n_in,
                              void* d_out, int out_size) {
    const float* x = nullptr;
    const float* w[4] = {nullptr,nullptr,nullptr,nullptr};
    const float* pcm[4] = {nullptr,nullptr,nullptr,nullptr};
    const float* Wout = nullptr;
    for (int i = 0; i < n_in; i++) {
        switch (in_sizes[i]) {
            case 131072: x = (const float*)d_in[i]; break;
            case 2080:  w[0] = (const float*)d_in[i]; break;
            case 4120:  w[1] = (const float*)d_in[i]; break;
            case 6160:  w[2] = (const float*)d_in[i]; break;
            case 10240: w[3] = (const float*)d_in[i]; break;
            case 3688:  pcm[0] = (const float*)d_in[i]; break;
            case 3280:  pcm[1] = (const float*)d_in[i]; break;
            case 2872:  pcm[2] = (const float*)d_in[i]; break;
            case 2056:  pcm[3] = (const float*)d_in[i]; break;
            case 1600:  Wout = (const float*)d_in[i]; break;
            default: break;
        }
    }
    float* out = (float*)d_out;

    cudaFuncSetAttribute(k_all, cudaFuncAttributeMaxDynamicSharedMemorySize, SM_BYTES);

    k_all<<<NBLK, 256, SM_BYTES>>>(x, w[0], w[1], w[2], w[3],
                                   pcm[0], pcm[1], pcm[2], pcm[3], Wout, out);
    (void)out_size;
}